// round 9
// baseline (speedup 1.0000x reference)
#include <cuda_runtime.h>
#include <cuda_fp16.h>
#include <cuda_bf16.h>

#define DIM 256
#define OUT 64
#define ALPHA 0.2f
#define N_MAX 50048
#define E_MAX 1600000
#define SCAN_B 1024
#define MAX_SCAN_BLOCKS ((N_MAX + SCAN_B - 1) / SCAN_B)

// Scratch (device globals — no allocation allowed)
__device__ __half g_h[N_MAX * OUT];   // h = x @ W (fp16; consumed only by agg)
__device__ float  g_s1[N_MAX];
__device__ float  g_s2[N_MAX];
__device__ int    g_deg[N_MAX];       // histogram (kept as CSR lengths)
__device__ int    g_off[N_MAX];       // block-local exclusive offsets
__device__ int    g_blksum[MAX_SCAN_BLOCKS];
__device__ int    g_rank[E_MAX];      // edge rank within its src (from hist)
__device__ int    g_csr[E_MAX];       // dst indices grouped by src

// ---------------------------------------------------------------------------
// Packed fp32x2 helpers (Blackwell FFMA2 — only reachable via PTX)
// ---------------------------------------------------------------------------
__device__ __forceinline__ unsigned long long pack2(float lo, float hi) {
    unsigned long long r;
    asm("mov.b64 %0, {%1, %2};" : "=l"(r) : "f"(lo), "f"(hi));
    return r;
}
__device__ __forceinline__ void unpack2(unsigned long long v, float& lo, float& hi) {
    asm("mov.b64 {%0, %1}, %2;" : "=f"(lo), "=f"(hi) : "l"(v));
}
__device__ __forceinline__ void ffma2(unsigned long long& acc,
                                      unsigned long long a, unsigned long long b) {
    asm("fma.rn.f32x2 %0, %1, %2, %0;" : "+l"(acc) : "l"(a), "l"(b));
}

// ---------------------------------------------------------------------------
// Zero degree counters
// ---------------------------------------------------------------------------
__global__ void zero_kernel(int n) {
    int i = blockIdx.x * blockDim.x + threadIdx.x;
    if (i < n) g_deg[i] = 0;
}

// ---------------------------------------------------------------------------
// Histogram: degree per src node; atomic old value = rank of edge within src.
// ---------------------------------------------------------------------------
__global__ void hist_kernel(const int* __restrict__ ei, int e) {
    int i = blockIdx.x * blockDim.x + threadIdx.x;
    if (i < e) g_rank[i] = atomicAdd(&g_deg[ei[i]], 1);
}

// ---------------------------------------------------------------------------
// Scan stage 1: block-local exclusive scan (shuffle-based), 49 blocks
// ---------------------------------------------------------------------------
__global__ void scan1_kernel(int n) {
    int t = threadIdx.x, lane = t & 31, wid = t >> 5;
    int i = blockIdx.x * SCAN_B + t;
    int v = (i < n) ? g_deg[i] : 0;
    int xv = v;
#pragma unroll
    for (int off = 1; off < 32; off <<= 1) {
        int y = __shfl_up_sync(0xFFFFFFFFu, xv, off);
        if (lane >= off) xv += y;
    }
    __shared__ int wsum[32];
    if (lane == 31) wsum[wid] = xv;
    __syncthreads();
    if (wid == 0) {
        int s = wsum[lane];
#pragma unroll
        for (int off = 1; off < 32; off <<= 1) {
            int y = __shfl_up_sync(0xFFFFFFFFu, s, off);
            if (lane >= off) s += y;
        }
        wsum[lane] = s;
    }
    __syncthreads();
    int incl = xv + (wid ? wsum[wid - 1] : 0);
    if (i < n) g_off[i] = incl - v;
    if (t == SCAN_B - 1) g_blksum[blockIdx.x] = incl;
}

// ---------------------------------------------------------------------------
// Scan stage 2: exclusive scan of block sums (single small block)
// ---------------------------------------------------------------------------
__global__ void scan2_kernel(int nb) {
    __shared__ int sh[64];
    int t = threadIdx.x;
    int v = (t < nb) ? g_blksum[t] : 0;
    sh[t] = v;
    __syncthreads();
#pragma unroll
    for (int off = 1; off < 64; off <<= 1) {
        int add = (t >= off) ? sh[t - off] : 0;
        __syncthreads();
        sh[t] += add;
        __syncthreads();
    }
    if (t < nb) g_blksum[t] = sh[t] - v;  // exclusive
}

// ---------------------------------------------------------------------------
// Scatter (atomic-free): pos = off[src] + blksum[src>>10] + rank[i]
// ---------------------------------------------------------------------------
__global__ void scatter_kernel(const int* __restrict__ ei, int e) {
    int i = blockIdx.x * blockDim.x + threadIdx.x;
    if (i >= e) return;
    int src = ei[i];
    int dst = ei[e + i];
    g_csr[g_off[src] + g_blksum[src >> 10] + g_rank[i]] = dst;
}

// ---------------------------------------------------------------------------
// h = x @ W with fused scores (runs on side stream, overlapped with CSR build)
// ---------------------------------------------------------------------------
__global__ void gemm_kernel(const float* __restrict__ x,
                            const float* __restrict__ W,
                            const float* __restrict__ a,
                            int n) {
    int gid = blockIdx.x * blockDim.x + threadIdx.x;
    int grp = gid >> 3;          // 4-row group index
    int cb  = (gid & 7) << 3;    // column base (0,8,...,56)
    int r0  = grp << 2;
    if (r0 >= n) return;

    int r1 = min(r0 + 1, n - 1);
    int r2 = min(r0 + 2, n - 1);
    int r3 = min(r0 + 3, n - 1);
    const float4* xp[4] = {
        reinterpret_cast<const float4*>(x + (size_t)r0 * DIM),
        reinterpret_cast<const float4*>(x + (size_t)r1 * DIM),
        reinterpret_cast<const float4*>(x + (size_t)r2 * DIM),
        reinterpret_cast<const float4*>(x + (size_t)r3 * DIM)};

    unsigned long long acc[4][4];
#pragma unroll
    for (int r = 0; r < 4; r++)
#pragma unroll
        for (int p = 0; p < 4; p++) acc[r][p] = 0ULL;

    for (int d4 = 0; d4 < DIM / 4; d4++) {
        float xs[4][4];
#pragma unroll
        for (int r = 0; r < 4; r++) {
            float4 xv = xp[r][d4];
            xs[r][0] = xv.x; xs[r][1] = xv.y; xs[r][2] = xv.z; xs[r][3] = xv.w;
        }
#pragma unroll
        for (int dd = 0; dd < 4; dd++) {
            int d = (d4 << 2) + dd;
            const ulonglong2* wp =
                reinterpret_cast<const ulonglong2*>(W + (size_t)d * OUT + cb);
            ulonglong2 wA = wp[0];
            ulonglong2 wB = wp[1];
#pragma unroll
            for (int r = 0; r < 4; r++) {
                unsigned long long xx = pack2(xs[r][dd], xs[r][dd]);
                ffma2(acc[r][0], wA.x, xx);
                ffma2(acc[r][1], wA.y, xx);
                ffma2(acc[r][2], wB.x, xx);
                ffma2(acc[r][3], wB.y, xx);
            }
        }
    }

    float a1v[8], a2v[8];
#pragma unroll
    for (int c = 0; c < 8; c++) {
        a1v[c] = a[cb + c];
        a2v[c] = a[OUT + cb + c];
    }

#pragma unroll
    for (int r = 0; r < 4; r++) {
        int row = r0 + r;
        if (row >= n) break;
        float o[8];
        unpack2(acc[r][0], o[0], o[1]);
        unpack2(acc[r][1], o[2], o[3]);
        unpack2(acc[r][2], o[4], o[5]);
        unpack2(acc[r][3], o[6], o[7]);

        __half2 hp[4];
#pragma unroll
        for (int p = 0; p < 4; p++)
            hp[p] = __floats2half2_rn(o[2 * p], o[2 * p + 1]);
        *reinterpret_cast<uint4*>(g_h + (size_t)row * OUT + cb) =
            *reinterpret_cast<uint4*>(hp);

        float p1 = 0.f, p2 = 0.f;
#pragma unroll
        for (int c = 0; c < 8; c++) {
            p1 += o[c] * a1v[c];
            p2 += o[c] * a2v[c];
        }
#pragma unroll
        for (int off = 4; off > 0; off >>= 1) {
            p1 += __shfl_down_sync(0xFFFFFFFFu, p1, off, 8);
            p2 += __shfl_down_sync(0xFFFFFFFFu, p2, off, 8);
        }
        if ((gid & 7) == 0) {
            g_s1[row] = p1;
            g_s2[row] = p2;
        }
    }
}

// ---------------------------------------------------------------------------
// Aggregate: warp per node. Weights lane-parallel, gather fp16 h (unroll 16).
// ---------------------------------------------------------------------------
__global__ void agg_kernel(float* __restrict__ out, int n) {
    int warp = (blockIdx.x * blockDim.x + threadIdx.x) >> 5;
    int lane = threadIdx.x & 31;
    if (warp >= n) return;

    int start = g_off[warp] + g_blksum[warp >> 10];
    int len   = g_deg[warp];
    float s1n = g_s1[warp];

    float acc0 = 0.f, acc1 = 0.f, wsum = 0.f;

    for (int base = 0; base < len; base += 32) {
        int k = base + lane;
        int dstl = 0;
        float wl = 0.f;
        if (k < len) {
            dstl = g_csr[start + k];
            float lg = s1n + g_s2[dstl];
            float lr = lg > 0.f ? lg : ALPHA * lg;
            wl = __expf(-lr);
        }
        wsum += wl;
        int m = len - base;
        if (m >= 32) {
#pragma unroll 16
            for (int j = 0; j < 32; j++) {
                int   d = __shfl_sync(0xFFFFFFFFu, dstl, j);
                float w = __shfl_sync(0xFFFFFFFFu, wl, j);
                __half2 hv = *reinterpret_cast<const __half2*>(
                    g_h + (size_t)d * OUT + lane * 2);
                float2 f = __half22float2(hv);
                acc0 += w * f.x;
                acc1 += w * f.y;
            }
        } else {
            for (int j = 0; j < m; j++) {
                int   d = __shfl_sync(0xFFFFFFFFu, dstl, j);
                float w = __shfl_sync(0xFFFFFFFFu, wl, j);
                __half2 hv = *reinterpret_cast<const __half2*>(
                    g_h + (size_t)d * OUT + lane * 2);
                float2 f = __half22float2(hv);
                acc0 += w * f.x;
                acc1 += w * f.y;
            }
        }
    }

#pragma unroll
    for (int off = 16; off > 0; off >>= 1)
        wsum += __shfl_xor_sync(0xFFFFFFFFu, wsum, off);

    float inv = 1.0f / wsum;
    float v0 = acc0 * inv;
    float v1 = acc1 * inv;
    out[(size_t)warp * OUT + lane * 2]     = v0 > 0.f ? v0 : expm1f(v0);
    out[(size_t)warp * OUT + lane * 2 + 1] = v1 > 0.f ? v1 : expm1f(v1);
}

extern "C" void kernel_launch(void* const* d_in, const int* in_sizes, int n_in,
                              void* d_out, int out_size) {
    const float* x  = (const float*)d_in[0];
    const int*   ei = (const int*)d_in[1];
    const float* W  = (const float*)d_in[2];
    const float* a  = (const float*)d_in[3];
    float* out = (float*)d_out;

    int n = in_sizes[0] / DIM;   // 50000
    int e = in_sizes[1] / 2;     // 1600000
    int nb = (n + SCAN_B - 1) / SCAN_B;

    // One-time creation of side stream + events (no device memory involved).
    static cudaStream_t s2 = nullptr;
    static cudaEvent_t ev_fork = nullptr, ev_join = nullptr;
    if (s2 == nullptr) {
        cudaStreamCreateWithFlags(&s2, cudaStreamNonBlocking);
        cudaEventCreateWithFlags(&ev_fork, cudaEventDisableTiming);
        cudaEventCreateWithFlags(&ev_join, cudaEventDisableTiming);
    }

    // Fork: side stream branches off before any main-stream kernels.
    cudaEventRecord(ev_fork, 0);
    cudaStreamWaitEvent(s2, ev_fork, 0);

    // Main chain (launches 1-3)
    zero_kernel<<<(n + 255) / 256, 256>>>(n);
    hist_kernel<<<(e + 255) / 256, 256>>>(ei, e);
    scan1_kernel<<<nb, SCAN_B>>>(n);

    // gemm as launch #4 (dependency-free graph node — still fully overlapped;
    // placed here so ncu's fixed sample slot lands on it)
    int gemm_threads = ((n + 3) / 4) * 8;
    gemm_kernel<<<(gemm_threads + 255) / 256, 256, 0, s2>>>(x, W, a, n);
    cudaEventRecord(ev_join, s2);

    scan2_kernel<<<1, 64>>>(nb);
    scatter_kernel<<<(e + 255) / 256, 256>>>(ei, e);

    // Join: agg needs both chains.
    cudaStreamWaitEvent(0, ev_join, 0);
    agg_kernel<<<((long long)n * 32 + 255) / 256, 256>>>(out, n);
}

// round 10
// speedup vs baseline: 1.0952x; 1.0952x over previous
#include <cuda_runtime.h>
#include <cuda_fp16.h>
#include <cuda_bf16.h>

#define DIM 256
#define OUT 64
#define ALPHA 0.2f
#define N_MAX 50048
#define E_MAX 1600000
#define SCAN_B 1024
#define MAX_SCAN_BLOCKS ((N_MAX + SCAN_B - 1) / SCAN_B)

// Scratch (device globals — no allocation allowed)
__device__ __half g_h[N_MAX * OUT];   // h = x @ W (fp16; consumed only by agg)
__device__ float  g_s1[N_MAX];
__device__ float  g_s2[N_MAX];
__device__ int    g_deg[N_MAX];       // histogram (kept as CSR lengths)
__device__ int    g_off[N_MAX];       // block-local exclusive offsets
__device__ int    g_blksum[MAX_SCAN_BLOCKS];
__device__ int    g_rank[E_MAX];      // edge rank within its src (from hist)
__device__ int    g_csr[E_MAX];       // dst indices grouped by src

// ---------------------------------------------------------------------------
// Packed fp32x2 helpers (Blackwell FFMA2 — only reachable via PTX)
// ---------------------------------------------------------------------------
__device__ __forceinline__ unsigned long long pack2(float lo, float hi) {
    unsigned long long r;
    asm("mov.b64 %0, {%1, %2};" : "=l"(r) : "f"(lo), "f"(hi));
    return r;
}
__device__ __forceinline__ void unpack2(unsigned long long v, float& lo, float& hi) {
    asm("mov.b64 {%0, %1}, %2;" : "=f"(lo), "=f"(hi) : "l"(v));
}
__device__ __forceinline__ void ffma2(unsigned long long& acc,
                                      unsigned long long a, unsigned long long b) {
    asm("fma.rn.f32x2 %0, %1, %2, %0;" : "+l"(acc) : "l"(a), "l"(b));
}

// ---------------------------------------------------------------------------
// Zero degree counters
// ---------------------------------------------------------------------------
__global__ void zero_kernel(int n) {
    int i = blockIdx.x * blockDim.x + threadIdx.x;
    if (i < n) g_deg[i] = 0;
}

// ---------------------------------------------------------------------------
// Histogram: degree per src node; atomic old value = rank of edge within src.
// ---------------------------------------------------------------------------
__global__ void hist_kernel(const int* __restrict__ ei, int e) {
    int i = blockIdx.x * blockDim.x + threadIdx.x;
    if (i < e) g_rank[i] = atomicAdd(&g_deg[ei[i]], 1);
}

// ---------------------------------------------------------------------------
// Scan stage 1: block-local exclusive scan (shuffle-based), 49 blocks
// ---------------------------------------------------------------------------
__global__ void scan1_kernel(int n) {
    int t = threadIdx.x, lane = t & 31, wid = t >> 5;
    int i = blockIdx.x * SCAN_B + t;
    int v = (i < n) ? g_deg[i] : 0;
    int xv = v;
#pragma unroll
    for (int off = 1; off < 32; off <<= 1) {
        int y = __shfl_up_sync(0xFFFFFFFFu, xv, off);
        if (lane >= off) xv += y;
    }
    __shared__ int wsum[32];
    if (lane == 31) wsum[wid] = xv;
    __syncthreads();
    if (wid == 0) {
        int s = wsum[lane];
#pragma unroll
        for (int off = 1; off < 32; off <<= 1) {
            int y = __shfl_up_sync(0xFFFFFFFFu, s, off);
            if (lane >= off) s += y;
        }
        wsum[lane] = s;
    }
    __syncthreads();
    int incl = xv + (wid ? wsum[wid - 1] : 0);
    if (i < n) g_off[i] = incl - v;
    if (t == SCAN_B - 1) g_blksum[blockIdx.x] = incl;
}

// ---------------------------------------------------------------------------
// Scan stage 2: exclusive scan of block sums (single small block)
// ---------------------------------------------------------------------------
__global__ void scan2_kernel(int nb) {
    __shared__ int sh[64];
    int t = threadIdx.x;
    int v = (t < nb) ? g_blksum[t] : 0;
    sh[t] = v;
    __syncthreads();
#pragma unroll
    for (int off = 1; off < 64; off <<= 1) {
        int add = (t >= off) ? sh[t - off] : 0;
        __syncthreads();
        sh[t] += add;
        __syncthreads();
    }
    if (t < nb) g_blksum[t] = sh[t] - v;  // exclusive
}

// ---------------------------------------------------------------------------
// Scatter (atomic-free): pos = off[src] + blksum[src>>10] + rank[i]
// ---------------------------------------------------------------------------
__global__ void scatter_kernel(const int* __restrict__ ei, int e) {
    int i = blockIdx.x * blockDim.x + threadIdx.x;
    if (i >= e) return;
    int src = ei[i];
    int dst = ei[e + i];
    g_csr[g_off[src] + g_blksum[src >> 10] + g_rank[i]] = dst;
}

// ---------------------------------------------------------------------------
// h = x @ W with fused scores.  W staged in 64KB shared memory: all W reads
// move off the L1 tex pipe (which was 66% saturated) onto the LDS pipe,
// leaving L1 free to stream x.  4 rows x 8 cols per thread, FFMA2 mainloop.
// ---------------------------------------------------------------------------
__global__ void __launch_bounds__(256)
gemm_kernel(const float* __restrict__ x,
            const float* __restrict__ W,
            const float* __restrict__ a,
            int n) {
    extern __shared__ float sW[];   // [DIM * OUT] = 16384 floats = 64KB

    // Cooperative W load: 256 threads x 16 float4 = 4096 float4 = full W
    {
        const float4* W4 = reinterpret_cast<const float4*>(W);
        float4* sW4 = reinterpret_cast<float4*>(sW);
#pragma unroll
        for (int i = 0; i < 16; i++)
            sW4[threadIdx.x + i * 256] = W4[threadIdx.x + i * 256];
    }
    __syncthreads();

    int gid = blockIdx.x * 256 + threadIdx.x;
    int grp = gid >> 3;          // 4-row group index
    int cb  = (gid & 7) << 3;    // column base (0,8,...,56)
    int r0  = grp << 2;
    if (r0 >= n) return;

    int r1 = min(r0 + 1, n - 1);
    int r2 = min(r0 + 2, n - 1);
    int r3 = min(r0 + 3, n - 1);
    const float4* xp[4] = {
        reinterpret_cast<const float4*>(x + (size_t)r0 * DIM),
        reinterpret_cast<const float4*>(x + (size_t)r1 * DIM),
        reinterpret_cast<const float4*>(x + (size_t)r2 * DIM),
        reinterpret_cast<const float4*>(x + (size_t)r3 * DIM)};

    unsigned long long acc[4][4];
#pragma unroll
    for (int r = 0; r < 4; r++)
#pragma unroll
        for (int p = 0; p < 4; p++) acc[r][p] = 0ULL;

    for (int d4 = 0; d4 < DIM / 4; d4++) {
        float xs[4][4];
#pragma unroll
        for (int r = 0; r < 4; r++) {
            float4 xv = xp[r][d4];
            xs[r][0] = xv.x; xs[r][1] = xv.y; xs[r][2] = xv.z; xs[r][3] = xv.w;
        }
#pragma unroll
        for (int dd = 0; dd < 4; dd++) {
            int d = (d4 << 2) + dd;
            const ulonglong2* wp =
                reinterpret_cast<const ulonglong2*>(sW + d * OUT + cb);
            ulonglong2 wA = wp[0];   // cols cb+0..3 (from smem)
            ulonglong2 wB = wp[1];   // cols cb+4..7 (from smem)
#pragma unroll
            for (int r = 0; r < 4; r++) {
                unsigned long long xx = pack2(xs[r][dd], xs[r][dd]);
                ffma2(acc[r][0], wA.x, xx);
                ffma2(acc[r][1], wA.y, xx);
                ffma2(acc[r][2], wB.x, xx);
                ffma2(acc[r][3], wB.y, xx);
            }
        }
    }

    float a1v[8], a2v[8];
#pragma unroll
    for (int c = 0; c < 8; c++) {
        a1v[c] = a[cb + c];
        a2v[c] = a[OUT + cb + c];
    }

#pragma unroll
    for (int r = 0; r < 4; r++) {
        int row = r0 + r;
        if (row >= n) break;
        float o[8];
        unpack2(acc[r][0], o[0], o[1]);
        unpack2(acc[r][1], o[2], o[3]);
        unpack2(acc[r][2], o[4], o[5]);
        unpack2(acc[r][3], o[6], o[7]);

        __half2 hp[4];
#pragma unroll
        for (int p = 0; p < 4; p++)
            hp[p] = __floats2half2_rn(o[2 * p], o[2 * p + 1]);
        *reinterpret_cast<uint4*>(g_h + (size_t)row * OUT + cb) =
            *reinterpret_cast<uint4*>(hp);

        float p1 = 0.f, p2 = 0.f;
#pragma unroll
        for (int c = 0; c < 8; c++) {
            p1 += o[c] * a1v[c];
            p2 += o[c] * a2v[c];
        }
#pragma unroll
        for (int off = 4; off > 0; off >>= 1) {
            p1 += __shfl_down_sync(0xFFFFFFFFu, p1, off, 8);
            p2 += __shfl_down_sync(0xFFFFFFFFu, p2, off, 8);
        }
        if ((gid & 7) == 0) {
            g_s1[row] = p1;
            g_s2[row] = p2;
        }
    }
}

// ---------------------------------------------------------------------------
// Aggregate: warp per node. Weights lane-parallel, gather fp16 h (unroll 8).
// ---------------------------------------------------------------------------
__global__ void agg_kernel(float* __restrict__ out, int n) {
    int warp = (blockIdx.x * blockDim.x + threadIdx.x) >> 5;
    int lane = threadIdx.x & 31;
    if (warp >= n) return;

    int start = g_off[warp] + g_blksum[warp >> 10];
    int len   = g_deg[warp];
    float s1n = g_s1[warp];

    float acc0 = 0.f, acc1 = 0.f, wsum = 0.f;

    for (int base = 0; base < len; base += 32) {
        int k = base + lane;
        int dstl = 0;
        float wl = 0.f;
        if (k < len) {
            dstl = g_csr[start + k];
            float lg = s1n + g_s2[dstl];
            float lr = lg > 0.f ? lg : ALPHA * lg;
            wl = __expf(-lr);
        }
        wsum += wl;
        int m = len - base;
        if (m >= 32) {
#pragma unroll 8
            for (int j = 0; j < 32; j++) {
                int   d = __shfl_sync(0xFFFFFFFFu, dstl, j);
                float w = __shfl_sync(0xFFFFFFFFu, wl, j);
                __half2 hv = *reinterpret_cast<const __half2*>(
                    g_h + (size_t)d * OUT + lane * 2);
                float2 f = __half22float2(hv);
                acc0 += w * f.x;
                acc1 += w * f.y;
            }
        } else {
            for (int j = 0; j < m; j++) {
                int   d = __shfl_sync(0xFFFFFFFFu, dstl, j);
                float w = __shfl_sync(0xFFFFFFFFu, wl, j);
                __half2 hv = *reinterpret_cast<const __half2*>(
                    g_h + (size_t)d * OUT + lane * 2);
                float2 f = __half22float2(hv);
                acc0 += w * f.x;
                acc1 += w * f.y;
            }
        }
    }

#pragma unroll
    for (int off = 16; off > 0; off >>= 1)
        wsum += __shfl_xor_sync(0xFFFFFFFFu, wsum, off);

    float inv = 1.0f / wsum;
    float v0 = acc0 * inv;
    float v1 = acc1 * inv;
    out[(size_t)warp * OUT + lane * 2]     = v0 > 0.f ? v0 : expm1f(v0);
    out[(size_t)warp * OUT + lane * 2 + 1] = v1 > 0.f ? v1 : expm1f(v1);
}

extern "C" void kernel_launch(void* const* d_in, const int* in_sizes, int n_in,
                              void* d_out, int out_size) {
    const float* x  = (const float*)d_in[0];
    const int*   ei = (const int*)d_in[1];
    const float* W  = (const float*)d_in[2];
    const float* a  = (const float*)d_in[3];
    float* out = (float*)d_out;

    int n = in_sizes[0] / DIM;   // 50000
    int e = in_sizes[1] / 2;     // 1600000
    int nb = (n + SCAN_B - 1) / SCAN_B;

    // One-time creation of side stream + events + smem opt-in (no dev memory).
    static cudaStream_t s2 = nullptr;
    static cudaEvent_t ev_fork = nullptr, ev_join = nullptr;
    if (s2 == nullptr) {
        cudaStreamCreateWithFlags(&s2, cudaStreamNonBlocking);
        cudaEventCreateWithFlags(&ev_fork, cudaEventDisableTiming);
        cudaEventCreateWithFlags(&ev_join, cudaEventDisableTiming);
        cudaFuncSetAttribute(gemm_kernel,
                             cudaFuncAttributeMaxDynamicSharedMemorySize,
                             DIM * OUT * (int)sizeof(float));
    }

    // Fork: gemm FIRST on side stream (it is the critical path).
    cudaEventRecord(ev_fork, 0);
    cudaStreamWaitEvent(s2, ev_fork, 0);

    int gemm_threads = ((n + 3) / 4) * 8;
    gemm_kernel<<<(gemm_threads + 255) / 256, 256,
                  DIM * OUT * sizeof(float), s2>>>(x, W, a, n);
    cudaEventRecord(ev_join, s2);

    // CSR build chain on main stream — fully overlapped with gemm.
    zero_kernel<<<(n + 255) / 256, 256>>>(n);
    hist_kernel<<<(e + 255) / 256, 256>>>(ei, e);
    scan1_kernel<<<nb, SCAN_B>>>(n);
    scan2_kernel<<<1, 64>>>(nb);
    scatter_kernel<<<(e + 255) / 256, 256>>>(ei, e);

    // Join: agg needs both chains.
    cudaStreamWaitEvent(0, ev_join, 0);
    agg_kernel<<<((long long)n * 32 + 255) / 256, 256>>>(out, n);
}

// round 12
// speedup vs baseline: 1.6386x; 1.4962x over previous
#include <cuda_runtime.h>
#include <cuda_fp16.h>
#include <cuda_bf16.h>

#define DIM 256
#define OUT 64
#define ALPHA 0.2f
#define N_MAX 50048
#define E_MAX 1600000
#define SCAN_B 1024
#define MAX_SCAN_BLOCKS ((N_MAX + SCAN_B - 1) / SCAN_B)
#define WT_STRIDE 264   // padded half-stride for Wt rows (conflict-free LDS)

// Scratch (device globals — no allocation allowed)
__device__ __half g_h[N_MAX * OUT];   // h = x @ W (fp16; consumed only by agg)
__device__ float  g_s1[N_MAX];
__device__ float  g_s2[N_MAX];
__device__ int    g_deg[N_MAX];       // histogram (kept as CSR lengths)
__device__ int    g_off[N_MAX];       // block-local exclusive offsets
__device__ int    g_blksum[MAX_SCAN_BLOCKS];
__device__ int    g_rank[E_MAX];      // edge rank within its src (from hist)
__device__ int    g_csr[E_MAX];       // dst indices grouped by src

// bit-cast half2 -> u32 (register alias; no SASS cost)
__device__ __forceinline__ unsigned h2_as_u32(__half2 h) {
    return *reinterpret_cast<unsigned*>(&h);
}

// ---------------------------------------------------------------------------
// Zero degree counters
// ---------------------------------------------------------------------------
__global__ void zero_kernel(int n) {
    int i = blockIdx.x * blockDim.x + threadIdx.x;
    if (i < n) g_deg[i] = 0;
}

// ---------------------------------------------------------------------------
// Histogram: degree per src node; atomic old value = rank of edge within src.
// ---------------------------------------------------------------------------
__global__ void hist_kernel(const int* __restrict__ ei, int e) {
    int i = blockIdx.x * blockDim.x + threadIdx.x;
    if (i < e) g_rank[i] = atomicAdd(&g_deg[ei[i]], 1);
}

// ---------------------------------------------------------------------------
// Scan stage 1: block-local exclusive scan (shuffle-based), 49 blocks
// ---------------------------------------------------------------------------
__global__ void scan1_kernel(int n) {
    int t = threadIdx.x, lane = t & 31, wid = t >> 5;
    int i = blockIdx.x * SCAN_B + t;
    int v = (i < n) ? g_deg[i] : 0;
    int xv = v;
#pragma unroll
    for (int off = 1; off < 32; off <<= 1) {
        int y = __shfl_up_sync(0xFFFFFFFFu, xv, off);
        if (lane >= off) xv += y;
    }
    __shared__ int wsum[32];
    if (lane == 31) wsum[wid] = xv;
    __syncthreads();
    if (wid == 0) {
        int s = wsum[lane];
#pragma unroll
        for (int off = 1; off < 32; off <<= 1) {
            int y = __shfl_up_sync(0xFFFFFFFFu, s, off);
            if (lane >= off) s += y;
        }
        wsum[lane] = s;
    }
    __syncthreads();
    int incl = xv + (wid ? wsum[wid - 1] : 0);
    if (i < n) g_off[i] = incl - v;
    if (t == SCAN_B - 1) g_blksum[blockIdx.x] = incl;
}

// ---------------------------------------------------------------------------
// Scan stage 2: exclusive scan of block sums (single small block)
// ---------------------------------------------------------------------------
__global__ void scan2_kernel(int nb) {
    __shared__ int sh[64];
    int t = threadIdx.x;
    int v = (t < nb) ? g_blksum[t] : 0;
    sh[t] = v;
    __syncthreads();
#pragma unroll
    for (int off = 1; off < 64; off <<= 1) {
        int add = (t >= off) ? sh[t - off] : 0;
        __syncthreads();
        sh[t] += add;
        __syncthreads();
    }
    if (t < nb) g_blksum[t] = sh[t] - v;  // exclusive
}

// ---------------------------------------------------------------------------
// Scatter (atomic-free): pos = off[src] + blksum[src>>10] + rank[i]
// ---------------------------------------------------------------------------
__global__ void scatter_kernel(const int* __restrict__ ei, int e) {
    int i = blockIdx.x * blockDim.x + threadIdx.x;
    if (i >= e) return;
    int src = ei[i];
    int dst = ei[e + i];
    g_csr[g_off[src] + g_blksum[src >> 10] + g_rank[i]] = dst;
}

// ---------------------------------------------------------------------------
// h = x @ W via tensor cores (mma.sync m16n8k16, fp16 in / fp32 accumulate).
// One warp computes a 16x64 output tile. W is converted to fp16 once per
// block into transposed smem Wt[n][k] (padded stride -> conflict-free LDS).
// Fused epilogue: fp16 h store + s1/s2 attention scores.
// ---------------------------------------------------------------------------
__global__ void __launch_bounds__(256)
gemm_kernel(const float* __restrict__ x,
            const float* __restrict__ W,
            const float* __restrict__ a,
            int n) {
    __shared__ __half sWt[OUT * WT_STRIDE];   // 64 x 264 halves = 33 KB

    // Prologue: convert W [256,64] fp32 -> Wt [64,264] fp16 (transposed)
    for (int j = 0; j < 64; j++) {
        int idx = threadIdx.x + j * 256;      // 0..16383
        int k   = idx >> 6;                   // 0..255
        int nn  = idx & 63;                   // 0..63
        sWt[nn * WT_STRIDE + k] = __float2half(W[k * OUT + nn]);
    }
    __syncthreads();

    int warp = threadIdx.x >> 5;
    int lane = threadIdx.x & 31;
    int grp  = lane >> 2;                     // 0..7
    int tig  = lane & 3;                      // 0..3

    int rowBase = blockIdx.x * 128 + warp * 16;
    if (rowBase >= n) return;
    int rLo = rowBase + grp;
    int rHi = rowBase + grp + 8;
    int rLoC = min(rLo, n - 1);               // clamped for loads
    int rHiC = min(rHi, n - 1);

    const float2* x2 = reinterpret_cast<const float2*>(x);
    const float2* xLo = x2 + (size_t)rLoC * (DIM / 2);
    const float2* xHi = x2 + (size_t)rHiC * (DIM / 2);

    float acc[8][4];
#pragma unroll
    for (int t = 0; t < 8; t++)
#pragma unroll
        for (int c = 0; c < 4; c++) acc[t][c] = 0.f;

#pragma unroll 4
    for (int kc = 0; kc < 16; kc++) {
        int k0 = kc * 16;
        int kh = (k0 >> 1) + tig;             // float2 index of k0 + tig*2

        // A fragments: rows (grp, grp+8), k pairs (k0+tig*2, +8)
        float2 f0 = xLo[kh];
        float2 f1 = xHi[kh];
        float2 f2 = xLo[kh + 4];
        float2 f3 = xHi[kh + 4];
        unsigned a0 = h2_as_u32(__floats2half2_rn(f0.x, f0.y));
        unsigned a1 = h2_as_u32(__floats2half2_rn(f1.x, f1.y));
        unsigned a2 = h2_as_u32(__floats2half2_rn(f2.x, f2.y));
        unsigned a3 = h2_as_u32(__floats2half2_rn(f3.x, f3.y));

#pragma unroll
        for (int t = 0; t < 8; t++) {
            int nIdx = t * 8 + grp;
            const unsigned* wrow = reinterpret_cast<const unsigned*>(
                sWt + nIdx * WT_STRIDE + k0);
            unsigned b0 = wrow[tig];          // halves (k0+tig*2, +1)
            unsigned b1 = wrow[4 + tig];      // halves (k0+8+tig*2, +1)
            asm volatile(
                "mma.sync.aligned.m16n8k16.row.col.f32.f16.f16.f32 "
                "{%0,%1,%2,%3}, {%4,%5,%6,%7}, {%8,%9}, {%0,%1,%2,%3};"
                : "+f"(acc[t][0]), "+f"(acc[t][1]),
                  "+f"(acc[t][2]), "+f"(acc[t][3])
                : "r"(a0), "r"(a1), "r"(a2), "r"(a3), "r"(b0), "r"(b1));
        }
    }

    // Epilogue: store h (fp16) + fused scores
    float p1Lo = 0.f, p2Lo = 0.f, p1Hi = 0.f, p2Hi = 0.f;
#pragma unroll
    for (int t = 0; t < 8; t++) {
        int n0 = t * 8 + tig * 2;             // output column pair
        if (rLo < n)
            *reinterpret_cast<__half2*>(g_h + (size_t)rLo * OUT + n0) =
                __floats2half2_rn(acc[t][0], acc[t][1]);
        if (rHi < n)
            *reinterpret_cast<__half2*>(g_h + (size_t)rHi * OUT + n0) =
                __floats2half2_rn(acc[t][2], acc[t][3]);
        float2 a1v = *reinterpret_cast<const float2*>(a + n0);
        float2 a2v = *reinterpret_cast<const float2*>(a + OUT + n0);
        p1Lo += acc[t][0] * a1v.x + acc[t][1] * a1v.y;
        p2Lo += acc[t][0] * a2v.x + acc[t][1] * a2v.y;
        p1Hi += acc[t][2] * a1v.x + acc[t][3] * a1v.y;
        p2Hi += acc[t][2] * a2v.x + acc[t][3] * a2v.y;
    }
    // Reduce across the 4 lanes of the quad (same grp, tig 0..3)
#pragma unroll
    for (int off = 2; off > 0; off >>= 1) {
        p1Lo += __shfl_down_sync(0xFFFFFFFFu, p1Lo, off);
        p2Lo += __shfl_down_sync(0xFFFFFFFFu, p2Lo, off);
        p1Hi += __shfl_down_sync(0xFFFFFFFFu, p1Hi, off);
        p2Hi += __shfl_down_sync(0xFFFFFFFFu, p2Hi, off);
    }
    if (tig == 0) {
        if (rLo < n) { g_s1[rLo] = p1Lo; g_s2[rLo] = p2Lo; }
        if (rHi < n) { g_s1[rHi] = p1Hi; g_s2[rHi] = p2Hi; }
    }
}

// ---------------------------------------------------------------------------
// Aggregate: warp per node. Weights lane-parallel, gather fp16 h (unroll 8).
// ---------------------------------------------------------------------------
__global__ void agg_kernel(float* __restrict__ out, int n) {
    int warp = (blockIdx.x * blockDim.x + threadIdx.x) >> 5;
    int lane = threadIdx.x & 31;
    if (warp >= n) return;

    int start = g_off[warp] + g_blksum[warp >> 10];
    int len   = g_deg[warp];
    float s1n = g_s1[warp];

    float acc0 = 0.f, acc1 = 0.f, wsum = 0.f;

    for (int base = 0; base < len; base += 32) {
        int k = base + lane;
        int dstl = 0;
        float wl = 0.f;
        if (k < len) {
            dstl = g_csr[start + k];
            float lg = s1n + g_s2[dstl];
            float lr = lg > 0.f ? lg : ALPHA * lg;
            wl = __expf(-lr);
        }
        wsum += wl;
        int m = len - base;
        if (m >= 32) {
#pragma unroll 8
            for (int j = 0; j < 32; j++) {
                int   d = __shfl_sync(0xFFFFFFFFu, dstl, j);
                float w = __shfl_sync(0xFFFFFFFFu, wl, j);
                __half2 hv = *reinterpret_cast<const __half2*>(
                    g_h + (size_t)d * OUT + lane * 2);
                float2 f = __half22float2(hv);
                acc0 += w * f.x;
                acc1 += w * f.y;
            }
        } else {
            for (int j = 0; j < m; j++) {
                int   d = __shfl_sync(0xFFFFFFFFu, dstl, j);
                float w = __shfl_sync(0xFFFFFFFFu, wl, j);
                __half2 hv = *reinterpret_cast<const __half2*>(
                    g_h + (size_t)d * OUT + lane * 2);
                float2 f = __half22float2(hv);
                acc0 += w * f.x;
                acc1 += w * f.y;
            }
        }
    }

#pragma unroll
    for (int off = 16; off > 0; off >>= 1)
        wsum += __shfl_xor_sync(0xFFFFFFFFu, wsum, off);

    float inv = 1.0f / wsum;
    float v0 = acc0 * inv;
    float v1 = acc1 * inv;
    out[(size_t)warp * OUT + lane * 2]     = v0 > 0.f ? v0 : expm1f(v0);
    out[(size_t)warp * OUT + lane * 2 + 1] = v1 > 0.f ? v1 : expm1f(v1);
}

extern "C" void kernel_launch(void* const* d_in, const int* in_sizes, int n_in,
                              void* d_out, int out_size) {
    const float* x  = (const float*)d_in[0];
    const int*   ei = (const int*)d_in[1];
    const float* W  = (const float*)d_in[2];
    const float* a  = (const float*)d_in[3];
    float* out = (float*)d_out;

    int n = in_sizes[0] / DIM;   // 50000
    int e = in_sizes[1] / 2;     // 1600000
    int nb = (n + SCAN_B - 1) / SCAN_B;

    // One-time creation of side stream + events (no device memory involved).
    static cudaStream_t s2 = nullptr;
    static cudaEvent_t ev_fork = nullptr, ev_join = nullptr;
    if (s2 == nullptr) {
        cudaStreamCreateWithFlags(&s2, cudaStreamNonBlocking);
        cudaEventCreateWithFlags(&ev_fork, cudaEventDisableTiming);
        cudaEventCreateWithFlags(&ev_join, cudaEventDisableTiming);
    }

    // Fork: gemm on side stream, CSR build on main stream — independent.
    cudaEventRecord(ev_fork, 0);
    cudaStreamWaitEvent(s2, ev_fork, 0);

    int gemm_blocks = (n + 127) / 128;   // 16 rows/warp x 8 warps
    gemm_kernel<<<gemm_blocks, 256, 0, s2>>>(x, W, a, n);
    cudaEventRecord(ev_join, s2);

    // CSR build chain on main stream — fully overlapped with gemm.
    zero_kernel<<<(n + 255) / 256, 256>>>(n);
    hist_kernel<<<(e + 255) / 256, 256>>>(ei, e);
    scan1_kernel<<<nb, SCAN_B>>>(n);
    scan2_kernel<<<1, 64>>>(nb);
    scatter_kernel<<<(e + 255) / 256, 256>>>(ei, e);

    // Join: agg needs both chains.
    cudaStreamWaitEvent(0, ev_join, 0);
    agg_kernel<<<((long long)n * 32 + 255) / 256, 256>>>(out, n);
}